// round 6
// baseline (speedup 1.0000x reference)
#include <cuda_runtime.h>
#include <cstdint>
#include <math.h>

// StructPool: B=8, N=2048, D=64, K=16, 5 mean-field iterations.

#define BB 8
#define NN 2048
#define DD 64
#define KK 16
#define ITERS 5
#define GCH 16          // 128-row chunks (= mega blocks per batch)
#define JC 16           // j-chunks for the A passes
#define JCH 128
#define RPB 128
#define IBLK 256        // i-columns per bigpass block

// ---- scratch ----
__device__ float g_cspart[BB*GCH*DD];
__device__ float g_s[BB*NN*KK];                 // L at the end
__device__ float g_P[(size_t)BB*NN*JC*KK];      // [row][jc][16], 16 MB (pass 1 only)
__device__ float g_Gpart[BB*GCH*DD*KK];
__device__ float g_XOpart[BB*GCH*KK*DD];
__device__ float g_Apart[BB*(NN/IBLK)*JC*KK*KK];  // 1 MB
__device__ unsigned g_bar;

// ---- packed f32x2 ----
__device__ __forceinline__ unsigned long long pack2(float a) {
    unsigned long long r;
    asm("mov.b64 %0, {%1, %1};" : "=l"(r) : "f"(a));
    return r;
}
__device__ __forceinline__ unsigned long long fma2(unsigned long long a,
                                                   unsigned long long b,
                                                   unsigned long long c) {
    unsigned long long d;
    asm("fma.rn.f32x2 %0, %1, %2, %3;" : "=l"(d) : "l"(a), "l"(b), "l"(c));
    return d;
}
__device__ __forceinline__ float lo2(unsigned long long v) {
    return __uint_as_float((unsigned)(v & 0xffffffffu));
}
__device__ __forceinline__ float hi2(unsigned long long v) {
    return __uint_as_float((unsigned)(v >> 32));
}

// ---- 1/3. A pass, 2 output cols/thread.
// MODE 0: V = pool(X) (fused prep), writes P partials; resets g_bar.
// MODE 1: V = L (g_s); fused A_out partial (L^T t), NO P write.
template <int MODE>
__global__ void __launch_bounds__(128) bigpass5_kernel(const float* __restrict__ A,
                                                       const float* __restrict__ X) {
    __shared__ float smem[8192];                 // 32 KB
    float* sV = smem;                            // [JCH*KK] = 8 KB (loop phase)
    int b = blockIdx.y, jc = blockIdx.z, tid = threadIdx.x;
    int i0 = blockIdx.x * IBLK + tid * 2;
    int j0 = jc * JCH;
    const float* Ab = A + (size_t)b * NN * NN;

    if (MODE == 0) {
        if (blockIdx.x == 0 && b == 0 && jc == 0 && tid == 0) g_bar = 0u;
        const float4* xs = reinterpret_cast<const float4*>(
            X + ((size_t)b * NN + j0 + tid) * DD);
        float* dst = &sV[tid * KK];
#pragma unroll
        for (int p = 0; p < 16; p++) {
            float4 v = xs[p];
            dst[p] = (v.x + v.y + v.z + v.w) * 0.25f;
        }
    } else {
        const float4* src = reinterpret_cast<const float4*>(g_s + ((size_t)b * NN + j0) * KK);
        float4* dst = reinterpret_cast<float4*>(sV);
#pragma unroll
        for (int e = tid; e < JCH * KK / 4; e += 128) dst[e] = src[e];
    }
    __syncthreads();

    unsigned long long acc[2][8];
#pragma unroll
    for (int ii = 0; ii < 2; ii++)
#pragma unroll
        for (int p = 0; p < 8; p++) acc[ii][p] = 0ull;

#pragma unroll 4
    for (int j = 0; j < JCH; j++) {
        float2 a = __ldcs(reinterpret_cast<const float2*>(Ab + (size_t)(j0 + j) * NN + i0));
        unsigned long long aa0 = pack2(a.x), aa1 = pack2(a.y);
        const ulonglong2* vp = reinterpret_cast<const ulonglong2*>(sV + j * KK);
        ulonglong2 v0 = vp[0], v1 = vp[1], v2 = vp[2], v3 = vp[3];
        acc[0][0] = fma2(aa0, v0.x, acc[0][0]); acc[0][1] = fma2(aa0, v0.y, acc[0][1]);
        acc[0][2] = fma2(aa0, v1.x, acc[0][2]); acc[0][3] = fma2(aa0, v1.y, acc[0][3]);
        acc[0][4] = fma2(aa0, v2.x, acc[0][4]); acc[0][5] = fma2(aa0, v2.y, acc[0][5]);
        acc[0][6] = fma2(aa0, v3.x, acc[0][6]); acc[0][7] = fma2(aa0, v3.y, acc[0][7]);
        acc[1][0] = fma2(aa1, v0.x, acc[1][0]); acc[1][1] = fma2(aa1, v0.y, acc[1][1]);
        acc[1][2] = fma2(aa1, v1.x, acc[1][2]); acc[1][3] = fma2(aa1, v1.y, acc[1][3]);
        acc[1][4] = fma2(aa1, v2.x, acc[1][4]); acc[1][5] = fma2(aa1, v2.y, acc[1][5]);
        acc[1][6] = fma2(aa1, v3.x, acc[1][6]); acc[1][7] = fma2(aa1, v3.y, acc[1][7]);
    }

    if (MODE == 0) {
#pragma unroll
        for (int ii = 0; ii < 2; ii++) {
            float* P = g_P + (((size_t)b * NN + i0 + ii) * JC + jc) * KK;
            ulonglong2* Pv = reinterpret_cast<ulonglong2*>(P);
            Pv[0] = make_ulonglong2(acc[ii][0], acc[ii][1]);
            Pv[1] = make_ulonglong2(acc[ii][2], acc[ii][3]);
            Pv[2] = make_ulonglong2(acc[ii][4], acc[ii][5]);
            Pv[3] = make_ulonglong2(acc[ii][6], acc[ii][7]);
        }
    } else {
        // contract partial t with L: A_out partial = sum_i L[i]^T t[i]
        float* sT = smem;            // [IBLK*KK] = 16 KB (reuses sV)
        float* sL = smem + 4096;     // [IBLK*KK] = 16 KB
        __syncthreads();             // everyone done reading sV
#pragma unroll
        for (int ii = 0; ii < 2; ii++) {
            float* t = &sT[(tid * 2 + ii) * KK];
#pragma unroll
            for (int p = 0; p < 8; p++) { t[2*p] = lo2(acc[ii][p]); t[2*p+1] = hi2(acc[ii][p]); }
        }
        {
            const float4* Ls = reinterpret_cast<const float4*>(
                g_s + ((size_t)b * NN + blockIdx.x * IBLK) * KK);
            float4* dst = reinterpret_cast<float4*>(sL);
#pragma unroll
            for (int e = tid; e < IBLK * KK / 4; e += 128) dst[e] = Ls[e];
        }
        __syncthreads();
#pragma unroll
        for (int h = 0; h < 2; h++) {
            int pair = tid + h * 128;
            int k1 = pair >> 4, k2 = pair & 15;
            float s = 0.f;
#pragma unroll 8
            for (int i = 0; i < IBLK; i++)
                s += sL[i * KK + k1] * sT[i * KK + k2];
            g_Apart[((((size_t)b * (NN/IBLK) + blockIdx.x) * JC) + jc) * 256 + pair] = s;
        }
    }
}

// ---- helpers ----
__device__ __forceinline__ float4 quad_softmax(float q0, float q1, float q2, float q3) {
    float m = fmaxf(fmaxf(q0, q1), fmaxf(q2, q3));
    m = fmaxf(m, __shfl_xor_sync(0xffffffffu, m, 1));
    m = fmaxf(m, __shfl_xor_sync(0xffffffffu, m, 2));
    float e0 = expf(q0-m), e1 = expf(q1-m), e2 = expf(q2-m), e3 = expf(q3-m);
    float es = e0 + e1 + e2 + e3;
    es += __shfl_xor_sync(0xffffffffu, es, 1);
    es += __shfl_xor_sync(0xffffffffu, es, 2);
    float si = 1.0f / es;
    return make_float4(e0*si, e1*si, e2*si, e3*si);
}

__device__ __forceinline__ void grid_barrier(int tid, unsigned target) {
    __syncthreads();
    if (tid == 0) {
        __threadfence();
        atomicAdd(&g_bar, 1u);
        while (*(volatile unsigned*)&g_bar < target) { }
    }
    __syncthreads();
}

// ---- 2. mega: P-reduce -> U -> 5 mean-field iterations -> L, XOpart ----
__global__ void __launch_bounds__(512) mega_kernel(const float* __restrict__ X,
                                                   const float* __restrict__ wf,
                                                   const float* __restrict__ wc) {
    __shared__ float sX[RPB * DD];
    __shared__ float ss[RPB * KK];
    __shared__ float sG[DD * KK];
    __shared__ float sM[KK * KK];
    __shared__ float cs[DD];
    int b = blockIdx.y, ch = blockIdx.x, tid = threadIdx.x;
    int lr = tid >> 2, q4 = tid & 3;
    size_t row = (size_t)b * NN + ch * RPB + lr;

    {
        const float4* src = reinterpret_cast<const float4*>(X + ((size_t)b * NN + ch * RPB) * DD);
        float4* dst = reinterpret_cast<float4*>(sX);
#pragma unroll
        for (int e = tid; e < RPB * DD / 4; e += 512) dst[e] = src[e];
    }
    if (tid < 256) {
        int k1 = tid >> 4, k2 = tid & 15;
        float mm = 0.f;
#pragma unroll
        for (int k = 0; k < KK; k++) mm += wf[k1*KK + k] * wc[k*KK + k2];
        sM[tid] = mm;
    }
    __syncthreads();

    float x[16];
#pragma unroll
    for (int p = 0; p < 4; p++) {
        float4 v = *reinterpret_cast<const float4*>(&sX[lr * DD + q4 * 16 + p * 4]);
        x[4*p] = v.x; x[4*p+1] = v.y; x[4*p+2] = v.z; x[4*p+3] = v.w;
    }
    float nsq = 0.f;
#pragma unroll
    for (int d = 0; d < 16; d++) nsq += x[d] * x[d];
    nsq += __shfl_xor_sync(0xffffffffu, nsq, 1);
    nsq += __shfl_xor_sync(0xffffffffu, nsq, 2);

    if (tid < 64) {
        float s = 0.f;
#pragma unroll 8
        for (int i = 0; i < RPB; i++) s += sX[i * DD + tid];
        g_cspart[(b * GCH + ch) * DD + tid] = s;
    }

    float4 u4 = make_float4(0.f, 0.f, 0.f, 0.f);
#pragma unroll
    for (int jc = 0; jc < JC; jc++) {
        float4 p = __ldcg(reinterpret_cast<const float4*>(g_P + (row * JC + jc) * KK + q4 * 4));
        u4.x += p.x; u4.y += p.y; u4.z += p.z; u4.w += p.w;
    }
    float lsum = u4.x + u4.y + u4.z + u4.w;
    lsum += __shfl_xor_sync(0xffffffffu, lsum, 1);
    lsum += __shfl_xor_sync(0xffffffffu, lsum, 2);
    float inv = 1.0f / lsum;
    float uq0 = tanhf(u4.x * inv), uq1 = tanhf(u4.y * inv);
    float uq2 = tanhf(u4.z * inv), uq3 = tanhf(u4.w * inv);
    {
        float4 sv = quad_softmax(uq0, uq1, uq2, uq3);
        *reinterpret_cast<float4*>(&ss[lr * KK + q4 * 4]) = sv;
    }
    __syncthreads();

    {
        int d = tid & 63, kb = (tid >> 6) * 2;
        float a0 = 0.f, a1 = 0.f;
#pragma unroll 4
        for (int i2 = 0; i2 < RPB; i2++) {
            float xx = sX[i2 * DD + d];
            a0 += xx * ss[i2 * KK + kb];
            a1 += xx * ss[i2 * KK + kb + 1];
        }
        float* gp = g_Gpart + (((size_t)b * GCH + ch) * DD + d) * KK + kb;
        gp[0] = a0; gp[1] = a1;
    }
    grid_barrier(tid, 1 * 128u);

    if (tid < 64) {
        float s = 0.f;
#pragma unroll
        for (int c = 0; c < GCH; c++) s += __ldcg(&g_cspart[(b * GCH + c) * DD + tid]);
        cs[tid] = s;
    }
    __syncthreads();
    float dot = 0.f;
#pragma unroll
    for (int d = 0; d < 16; d++) dot += x[d] * cs[q4 * 16 + d];
    dot += __shfl_xor_sync(0xffffffffu, dot, 1);
    dot += __shfl_xor_sync(0xffffffffu, dot, 2);
    float ninv = 1.0f / (dot - nsq);

    unsigned phase = 1;
#pragma unroll 1
    for (int it = 0; it < ITERS; it++) {
        bool last = (it == ITERS - 1);
        if (tid < 256) {
            float4 acc = make_float4(0.f, 0.f, 0.f, 0.f);
#pragma unroll
            for (int c2 = 0; c2 < GCH; c2++) {
                float4 p = __ldcg(reinterpret_cast<const float4*>(
                    g_Gpart + ((size_t)b * GCH + c2) * DD * KK + tid * 4));
                acc.x += p.x; acc.y += p.y; acc.z += p.z; acc.w += p.w;
            }
            *reinterpret_cast<float4*>(&sG[tid * 4]) = acc;
        }
        __syncthreads();

        float xg[KK];
#pragma unroll
        for (int k = 0; k < KK; k++) xg[k] = 0.f;
#pragma unroll
        for (int dd = 0; dd < 16; dd++) {
            float xd = x[dd];
            const float* g = &sG[(q4 * 16 + dd) * KK];
#pragma unroll
            for (int k = 0; k < KK; k++) xg[k] += xd * g[k];
        }
#pragma unroll
        for (int k = 0; k < KK; k++) {
            xg[k] += __shfl_xor_sync(0xffffffffu, xg[k], 1);
            xg[k] += __shfl_xor_sync(0xffffffffu, xg[k], 2);
        }

        float q0 = uq0, q1 = uq1, q2 = uq2, q3 = uq3;
#pragma unroll
        for (int k = 0; k < KK; k++) {
            float o = (xg[k] - nsq * ss[lr * KK + k]) * ninv;
            const float* Mr = &sM[k * KK + q4 * 4];
            q0 -= o * Mr[0]; q1 -= o * Mr[1]; q2 -= o * Mr[2]; q3 -= o * Mr[3];
        }
        float4 sv = quad_softmax(q0, q1, q2, q3);
        __syncthreads();
        *reinterpret_cast<float4*>(&ss[lr * KK + q4 * 4]) = sv;
        if (last) *reinterpret_cast<float4*>(g_s + row * KK + q4 * 4) = sv;
        __syncthreads();

        int d = tid & 63, kb = (tid >> 6) * 2;
        float a0 = 0.f, a1 = 0.f;
#pragma unroll 4
        for (int i2 = 0; i2 < RPB; i2++) {
            float xx = sX[i2 * DD + d];
            a0 += xx * ss[i2 * KK + kb];
            a1 += xx * ss[i2 * KK + kb + 1];
        }
        if (!last) {
            float* gp = g_Gpart + (((size_t)b * GCH + ch) * DD + d) * KK + kb;
            gp[0] = a0; gp[1] = a1;
            phase++;
            grid_barrier(tid, phase * 128u);
        } else {
            float* xp = g_XOpart + ((size_t)b * GCH + ch) * KK * DD;
            xp[(kb+0)*DD + d] = a0; xp[(kb+1)*DD + d] = a1;
        }
    }
}

// ---- 4. final: reduce XOpart -> X_out, reduce Apart -> A_out ----
__global__ void __launch_bounds__(256) final_kernel(float* __restrict__ out) {
    int b = blockIdx.x, tid = threadIdx.x;
    for (int e = tid; e < KK * DD; e += 256) {
        float s = 0.f;
#pragma unroll
        for (int ch = 0; ch < GCH; ch++)
            s += g_XOpart[((size_t)b * GCH + ch) * KK * DD + e];
        out[(size_t)b * KK * DD + e] = s;
    }
    float s = 0.f;
#pragma unroll 8
    for (int c = 0; c < (NN/IBLK) * JC; c++)
        s += g_Apart[((size_t)b * (NN/IBLK) * JC + c) * 256 + tid];
    out[(size_t)BB * KK * DD + b * 256 + tid] = s;
}

extern "C" void kernel_launch(void* const* d_in, const int* in_sizes, int n_in,
                              void* d_out, int out_size) {
    const float* X  = (const float*)d_in[0];
    const float* A  = (const float*)d_in[1];
    const float* wf = (const float*)d_in[2];
    const float* wc = (const float*)d_in[3];
    float* out = (float*)d_out;

    bigpass5_kernel<0><<<dim3(NN/IBLK, BB, JC), 128>>>(A, X);
    mega_kernel<<<dim3(GCH, BB), 512>>>(X, wf, wc);
    bigpass5_kernel<1><<<dim3(NN/IBLK, BB, JC), 128>>>(A, X);
    final_kernel<<<BB, 256>>>(out);
}

// round 7
// speedup vs baseline: 1.0661x; 1.0661x over previous
#include <cuda_runtime.h>
#include <cstdint>
#include <math.h>

// StructPool: B=8, N=2048, D=64, K=16, 5 mean-field iterations.

#define BB 8
#define NN 2048
#define DD 64
#define KK 16
#define ITERS 5
#define GCH 16          // 128-row chunks (= mega blocks per batch)
#define JC 16           // j-chunks for the A passes
#define JCH 128
#define RPB 128
#define IBLK 256        // i-columns per bigpass block
#define NW2 (NN/64)     // uint2 words per j-row (32)

// ---- scratch ----
__device__ float g_cspart[BB*GCH*DD];
__device__ float g_s[BB*NN*KK];                 // L at the end
__device__ float g_P[(size_t)BB*NN*JC*KK];      // [row][jc][16], 16 MB
__device__ float g_Gpart[BB*GCH*DD*KK];
__device__ uint2 g_Abits[(size_t)BB*NN*NW2];    // bit-packed A, 4 MB
__device__ unsigned g_bar;

// ---- packed f32x2 ----
__device__ __forceinline__ unsigned long long pack2(float a) {
    unsigned long long r;
    asm("mov.b64 %0, {%1, %1};" : "=l"(r) : "f"(a));
    return r;
}
__device__ __forceinline__ unsigned long long fma2(unsigned long long a,
                                                   unsigned long long b,
                                                   unsigned long long c) {
    unsigned long long d;
    asm("fma.rn.f32x2 %0, %1, %2, %3;" : "=l"(d) : "l"(a), "l"(b), "l"(c));
    return d;
}
__device__ __forceinline__ float lo2(unsigned long long v) {
    return __uint_as_float((unsigned)(v & 0xffffffffu));
}
__device__ __forceinline__ float hi2(unsigned long long v) {
    return __uint_as_float((unsigned)(v >> 32));
}
#define ONE2 0x3f8000003f800000ull

// ---- 1. pass 1: P partials from float A; emits bit-packed A; zeroes out+bar ----
__global__ void __launch_bounds__(128) bigpassA_kernel(const float* __restrict__ A,
                                                       const float* __restrict__ X,
                                                       float* __restrict__ out) {
    __shared__ float sV[JCH * KK];               // 8 KB
    int b = blockIdx.y, jc = blockIdx.z, tid = threadIdx.x;
    int warp = tid >> 5, lane = tid & 31;
    int i0 = blockIdx.x * IBLK + tid * 2;
    int j0 = jc * JCH;
    const float* Ab = A + (size_t)b * NN * NN;

    if (blockIdx.x == 0 && jc == 0) {            // zero out (8 blocks) + bar
        if (b == 0 && tid == 0) g_bar = 0u;
#pragma unroll
        for (int e = tid; e < KK * DD + KK * KK; e += 128) {
            if (e < KK * DD) out[(size_t)b * KK * DD + e] = 0.f;
            else out[(size_t)BB * KK * DD + b * KK * KK + (e - KK * DD)] = 0.f;
        }
    }

    {   // fused prep: pool(X) chunk
        const float4* xs = reinterpret_cast<const float4*>(X + ((size_t)b * NN + j0 + tid) * DD);
        float* dst = &sV[tid * KK];
#pragma unroll
        for (int p = 0; p < 16; p++) {
            float4 v = xs[p];
            dst[p] = (v.x + v.y + v.z + v.w) * 0.25f;
        }
    }
    __syncthreads();

    unsigned long long acc[2][8];
#pragma unroll
    for (int ii = 0; ii < 2; ii++)
#pragma unroll
        for (int p = 0; p < 8; p++) acc[ii][p] = 0ull;

#pragma unroll 4
    for (int j = 0; j < JCH; j++) {
        float2 a = __ldcs(reinterpret_cast<const float2*>(Ab + (size_t)(j0 + j) * NN + i0));
        // pack bits: lane l of warp w -> i = bx*256 + w*64 + 2l (+1)
        unsigned me = __ballot_sync(0xffffffffu, a.x != 0.f);
        unsigned mo = __ballot_sync(0xffffffffu, a.y != 0.f);
        if (lane == 0)
            g_Abits[((size_t)b * NN + j0 + j) * NW2 + blockIdx.x * 4 + warp] = make_uint2(me, mo);

        unsigned long long aa0 = pack2(a.x), aa1 = pack2(a.y);
        const ulonglong2* vp = reinterpret_cast<const ulonglong2*>(sV + j * KK);
        ulonglong2 v0 = vp[0], v1 = vp[1], v2 = vp[2], v3 = vp[3];
        acc[0][0] = fma2(aa0, v0.x, acc[0][0]); acc[0][1] = fma2(aa0, v0.y, acc[0][1]);
        acc[0][2] = fma2(aa0, v1.x, acc[0][2]); acc[0][3] = fma2(aa0, v1.y, acc[0][3]);
        acc[0][4] = fma2(aa0, v2.x, acc[0][4]); acc[0][5] = fma2(aa0, v2.y, acc[0][5]);
        acc[0][6] = fma2(aa0, v3.x, acc[0][6]); acc[0][7] = fma2(aa0, v3.y, acc[0][7]);
        acc[1][0] = fma2(aa1, v0.x, acc[1][0]); acc[1][1] = fma2(aa1, v0.y, acc[1][1]);
        acc[1][2] = fma2(aa1, v1.x, acc[1][2]); acc[1][3] = fma2(aa1, v1.y, acc[1][3]);
        acc[1][4] = fma2(aa1, v2.x, acc[1][4]); acc[1][5] = fma2(aa1, v2.y, acc[1][5]);
        acc[1][6] = fma2(aa1, v3.x, acc[1][6]); acc[1][7] = fma2(aa1, v3.y, acc[1][7]);
    }

#pragma unroll
    for (int ii = 0; ii < 2; ii++) {
        float* P = g_P + (((size_t)b * NN + i0 + ii) * JC + jc) * KK;
        ulonglong2* Pv = reinterpret_cast<ulonglong2*>(P);
        Pv[0] = make_ulonglong2(acc[ii][0], acc[ii][1]);
        Pv[1] = make_ulonglong2(acc[ii][2], acc[ii][3]);
        Pv[2] = make_ulonglong2(acc[ii][4], acc[ii][5]);
        Pv[3] = make_ulonglong2(acc[ii][6], acc[ii][7]);
    }
}

// ---- 3. pass 2: t = A@L from BIT-PACKED A; fused A_out partial -> atomicAdd ----
__global__ void __launch_bounds__(128) bigpassB_kernel(float* __restrict__ out) {
    __shared__ float smem[8192];                 // 32 KB
    float* sV = smem;                            // L chunk [JCH*KK] = 8 KB
    uint2* sB = reinterpret_cast<uint2*>(smem + 2048);   // [4][JCH] = 4 KB
    int b = blockIdx.y, jc = blockIdx.z, tid = threadIdx.x;
    int warp = tid >> 5, lane = tid & 31;
    int j0 = jc * JCH;

    {   // stage L chunk
        const float4* src = reinterpret_cast<const float4*>(g_s + ((size_t)b * NN + j0) * KK);
        float4* dst = reinterpret_cast<float4*>(sV);
#pragma unroll
        for (int e = tid; e < JCH * KK / 4; e += 128) dst[e] = src[e];
    }
    {   // stage bits: 512 uint2
#pragma unroll
        for (int e = tid; e < 4 * JCH; e += 128) {
            int j = e >> 2, ws = e & 3;
            sB[ws * JCH + j] = g_Abits[((size_t)b * NN + j0 + j) * NW2 + blockIdx.x * 4 + ws];
        }
    }
    __syncthreads();

    unsigned lm = 1u << lane;
    unsigned long long acc[2][8];
#pragma unroll
    for (int ii = 0; ii < 2; ii++)
#pragma unroll
        for (int p = 0; p < 8; p++) acc[ii][p] = 0ull;

#pragma unroll 4
    for (int j = 0; j < JCH; j++) {
        uint2 w = sB[warp * JCH + j];
        unsigned long long aa0 = (w.x & lm) ? ONE2 : 0ull;
        unsigned long long aa1 = (w.y & lm) ? ONE2 : 0ull;
        const ulonglong2* vp = reinterpret_cast<const ulonglong2*>(sV + j * KK);
        ulonglong2 v0 = vp[0], v1 = vp[1], v2 = vp[2], v3 = vp[3];
        acc[0][0] = fma2(aa0, v0.x, acc[0][0]); acc[0][1] = fma2(aa0, v0.y, acc[0][1]);
        acc[0][2] = fma2(aa0, v1.x, acc[0][2]); acc[0][3] = fma2(aa0, v1.y, acc[0][3]);
        acc[0][4] = fma2(aa0, v2.x, acc[0][4]); acc[0][5] = fma2(aa0, v2.y, acc[0][5]);
        acc[0][6] = fma2(aa0, v3.x, acc[0][6]); acc[0][7] = fma2(aa0, v3.y, acc[0][7]);
        acc[1][0] = fma2(aa1, v0.x, acc[1][0]); acc[1][1] = fma2(aa1, v0.y, acc[1][1]);
        acc[1][2] = fma2(aa1, v1.x, acc[1][2]); acc[1][3] = fma2(aa1, v1.y, acc[1][3]);
        acc[1][4] = fma2(aa1, v2.x, acc[1][4]); acc[1][5] = fma2(aa1, v2.y, acc[1][5]);
        acc[1][6] = fma2(aa1, v3.x, acc[1][6]); acc[1][7] = fma2(aa1, v3.y, acc[1][7]);
    }

    // A_out partial: stage t and L-of-this-i-range, contract 256x16 x 256x16
    float* sT = smem;            // [IBLK*KK] = 16 KB
    float* sL = smem + 4096;     // [IBLK*KK] = 16 KB
    __syncthreads();
#pragma unroll
    for (int ii = 0; ii < 2; ii++) {
        float* t = &sT[(tid * 2 + ii) * KK];
#pragma unroll
        for (int p = 0; p < 8; p++) { t[2*p] = lo2(acc[ii][p]); t[2*p+1] = hi2(acc[ii][p]); }
    }
    {
        const float4* Ls = reinterpret_cast<const float4*>(
            g_s + ((size_t)b * NN + blockIdx.x * IBLK) * KK);
        float4* dst = reinterpret_cast<float4*>(sL);
#pragma unroll
        for (int e = tid; e < IBLK * KK / 4; e += 128) dst[e] = Ls[e];
    }
    __syncthreads();
#pragma unroll
    for (int h = 0; h < 2; h++) {
        int pair = tid + h * 128;
        int k1 = pair >> 4, k2 = pair & 15;
        float s = 0.f;
#pragma unroll 8
        for (int i = 0; i < IBLK; i++)
            s += sL[i * KK + k1] * sT[i * KK + k2];
        atomicAdd(&out[(size_t)BB * KK * DD + b * KK * KK + pair], s);
    }
}

// ---- helpers ----
__device__ __forceinline__ float4 quad_softmax(float q0, float q1, float q2, float q3) {
    float m = fmaxf(fmaxf(q0, q1), fmaxf(q2, q3));
    m = fmaxf(m, __shfl_xor_sync(0xffffffffu, m, 1));
    m = fmaxf(m, __shfl_xor_sync(0xffffffffu, m, 2));
    float e0 = expf(q0-m), e1 = expf(q1-m), e2 = expf(q2-m), e3 = expf(q3-m);
    float es = e0 + e1 + e2 + e3;
    es += __shfl_xor_sync(0xffffffffu, es, 1);
    es += __shfl_xor_sync(0xffffffffu, es, 2);
    float si = 1.0f / es;
    return make_float4(e0*si, e1*si, e2*si, e3*si);
}

__device__ __forceinline__ void grid_barrier(int tid, unsigned target) {
    __syncthreads();
    if (tid == 0) {
        __threadfence();
        atomicAdd(&g_bar, 1u);
        while (*(volatile unsigned*)&g_bar < target) { }
    }
    __syncthreads();
}

// ---- 2. mega: P-reduce -> U -> 5 iterations -> L; X_out via atomicAdd ----
__global__ void __launch_bounds__(512) mega_kernel(const float* __restrict__ X,
                                                   const float* __restrict__ wf,
                                                   const float* __restrict__ wc,
                                                   float* __restrict__ out) {
    __shared__ float sX[RPB * DD];
    __shared__ float ss[RPB * KK];
    __shared__ float sG[DD * KK];
    __shared__ float sM[KK * KK];
    __shared__ float cs[DD];
    int b = blockIdx.y, ch = blockIdx.x, tid = threadIdx.x;
    int lr = tid >> 2, q4 = tid & 3;
    size_t row = (size_t)b * NN + ch * RPB + lr;

    {
        const float4* src = reinterpret_cast<const float4*>(X + ((size_t)b * NN + ch * RPB) * DD);
        float4* dst = reinterpret_cast<float4*>(sX);
#pragma unroll
        for (int e = tid; e < RPB * DD / 4; e += 512) dst[e] = src[e];
    }
    if (tid < 256) {
        int k1 = tid >> 4, k2 = tid & 15;
        float mm = 0.f;
#pragma unroll
        for (int k = 0; k < KK; k++) mm += wf[k1*KK + k] * wc[k*KK + k2];
        sM[tid] = mm;
    }
    __syncthreads();

    float x[16];
#pragma unroll
    for (int p = 0; p < 4; p++) {
        float4 v = *reinterpret_cast<const float4*>(&sX[lr * DD + q4 * 16 + p * 4]);
        x[4*p] = v.x; x[4*p+1] = v.y; x[4*p+2] = v.z; x[4*p+3] = v.w;
    }
    float nsq = 0.f;
#pragma unroll
    for (int d = 0; d < 16; d++) nsq += x[d] * x[d];
    nsq += __shfl_xor_sync(0xffffffffu, nsq, 1);
    nsq += __shfl_xor_sync(0xffffffffu, nsq, 2);

    if (tid < 64) {
        float s = 0.f;
#pragma unroll 8
        for (int i = 0; i < RPB; i++) s += sX[i * DD + tid];
        g_cspart[(b * GCH + ch) * DD + tid] = s;
    }

    float4 u4 = make_float4(0.f, 0.f, 0.f, 0.f);
#pragma unroll
    for (int jc = 0; jc < JC; jc++) {
        float4 p = __ldcg(reinterpret_cast<const float4*>(g_P + (row * JC + jc) * KK + q4 * 4));
        u4.x += p.x; u4.y += p.y; u4.z += p.z; u4.w += p.w;
    }
    float lsum = u4.x + u4.y + u4.z + u4.w;
    lsum += __shfl_xor_sync(0xffffffffu, lsum, 1);
    lsum += __shfl_xor_sync(0xffffffffu, lsum, 2);
    float inv = 1.0f / lsum;
    float uq0 = tanhf(u4.x * inv), uq1 = tanhf(u4.y * inv);
    float uq2 = tanhf(u4.z * inv), uq3 = tanhf(u4.w * inv);
    {
        float4 sv = quad_softmax(uq0, uq1, uq2, uq3);
        *reinterpret_cast<float4*>(&ss[lr * KK + q4 * 4]) = sv;
    }
    __syncthreads();

    {
        int d = tid & 63, kb = (tid >> 6) * 2;
        float a0 = 0.f, a1 = 0.f;
#pragma unroll 4
        for (int i2 = 0; i2 < RPB; i2++) {
            float xx = sX[i2 * DD + d];
            a0 += xx * ss[i2 * KK + kb];
            a1 += xx * ss[i2 * KK + kb + 1];
        }
        float* gp = g_Gpart + (((size_t)b * GCH + ch) * DD + d) * KK + kb;
        gp[0] = a0; gp[1] = a1;
    }
    grid_barrier(tid, 1 * 128u);

    if (tid < 64) {
        float s = 0.f;
#pragma unroll
        for (int c = 0; c < GCH; c++) s += __ldcg(&g_cspart[(b * GCH + c) * DD + tid]);
        cs[tid] = s;
    }
    __syncthreads();
    float dot = 0.f;
#pragma unroll
    for (int d = 0; d < 16; d++) dot += x[d] * cs[q4 * 16 + d];
    dot += __shfl_xor_sync(0xffffffffu, dot, 1);
    dot += __shfl_xor_sync(0xffffffffu, dot, 2);
    float ninv = 1.0f / (dot - nsq);

    unsigned phase = 1;
#pragma unroll 1
    for (int it = 0; it < ITERS; it++) {
        bool last = (it == ITERS - 1);
        if (tid < 256) {
            float4 acc = make_float4(0.f, 0.f, 0.f, 0.f);
#pragma unroll
            for (int c2 = 0; c2 < GCH; c2++) {
                float4 p = __ldcg(reinterpret_cast<const float4*>(
                    g_Gpart + ((size_t)b * GCH + c2) * DD * KK + tid * 4));
                acc.x += p.x; acc.y += p.y; acc.z += p.z; acc.w += p.w;
            }
            *reinterpret_cast<float4*>(&sG[tid * 4]) = acc;
        }
        __syncthreads();

        float xg[KK];
#pragma unroll
        for (int k = 0; k < KK; k++) xg[k] = 0.f;
#pragma unroll
        for (int dd = 0; dd < 16; dd++) {
            float xd = x[dd];
            const float* g = &sG[(q4 * 16 + dd) * KK];
#pragma unroll
            for (int k = 0; k < KK; k++) xg[k] += xd * g[k];
        }
#pragma unroll
        for (int k = 0; k < KK; k++) {
            xg[k] += __shfl_xor_sync(0xffffffffu, xg[k], 1);
            xg[k] += __shfl_xor_sync(0xffffffffu, xg[k], 2);
        }

        float q0 = uq0, q1 = uq1, q2 = uq2, q3 = uq3;
#pragma unroll
        for (int k = 0; k < KK; k++) {
            float o = (xg[k] - nsq * ss[lr * KK + k]) * ninv;
            const float* Mr = &sM[k * KK + q4 * 4];
            q0 -= o * Mr[0]; q1 -= o * Mr[1]; q2 -= o * Mr[2]; q3 -= o * Mr[3];
        }
        float4 sv = quad_softmax(q0, q1, q2, q3);
        __syncthreads();
        *reinterpret_cast<float4*>(&ss[lr * KK + q4 * 4]) = sv;
        if (last) *reinterpret_cast<float4*>(g_s + row * KK + q4 * 4) = sv;
        __syncthreads();

        int d = tid & 63, kb = (tid >> 6) * 2;
        float a0 = 0.f, a1 = 0.f;
#pragma unroll 4
        for (int i2 = 0; i2 < RPB; i2++) {
            float xx = sX[i2 * DD + d];
            a0 += xx * ss[i2 * KK + kb];
            a1 += xx * ss[i2 * KK + kb + 1];
        }
        if (!last) {
            float* gp = g_Gpart + (((size_t)b * GCH + ch) * DD + d) * KK + kb;
            gp[0] = a0; gp[1] = a1;
            phase++;
            grid_barrier(tid, phase * 128u);
        } else {
            atomicAdd(&out[(size_t)b * KK * DD + (kb+0) * DD + d], a0);
            atomicAdd(&out[(size_t)b * KK * DD + (kb+1) * DD + d], a1);
        }
    }
}

extern "C" void kernel_launch(void* const* d_in, const int* in_sizes, int n_in,
                              void* d_out, int out_size) {
    const float* X  = (const float*)d_in[0];
    const float* A  = (const float*)d_in[1];
    const float* wf = (const float*)d_in[2];
    const float* wc = (const float*)d_in[3];
    float* out = (float*)d_out;

    bigpassA_kernel<<<dim3(NN/IBLK, BB, JC), 128>>>(A, X, out);
    mega_kernel<<<dim3(GCH, BB), 512>>>(X, wf, wc, out);
    bigpassB_kernel<<<dim3(NN/IBLK, BB, JC), 128>>>(out);
}

// round 8
// speedup vs baseline: 1.1535x; 1.0820x over previous
#include <cuda_runtime.h>
#include <cstdint>
#include <math.h>

// StructPool: B=8, N=2048, D=64, K=16, 5 mean-field iterations.

#define BB 8
#define NN 2048
#define DD 64
#define KK 16
#define ITERS 5
#define GCH 16          // 128-row chunks (= mega blocks per batch)
#define JC 16           // j-chunks for the A passes
#define JCH 128
#define RPB 128
#define IBLK 256        // i-columns per bigpass block
#define NW2 (NN/64)     // uint2 words per j-row (32)

// ---- scratch ----
__device__ float g_cspart[BB*GCH*DD];
__device__ float g_s[BB*NN*KK];                 // L at the end
__device__ float g_P[(size_t)BB*NN*JC*KK];      // [row][jc][16], 16 MB
__device__ float g_Gpart[BB*GCH*DD*KK];
__device__ uint2 g_Abits[(size_t)BB*NN*NW2];    // bit-packed A, 4 MB
__device__ unsigned g_bar;

// ---- packed f32x2 ----
__device__ __forceinline__ unsigned long long pack2(float a) {
    unsigned long long r;
    asm("mov.b64 %0, {%1, %1};" : "=l"(r) : "f"(a));
    return r;
}
__device__ __forceinline__ unsigned long long fma2(unsigned long long a,
                                                   unsigned long long b,
                                                   unsigned long long c) {
    unsigned long long d;
    asm("fma.rn.f32x2 %0, %1, %2, %3;" : "=l"(d) : "l"(a), "l"(b), "l"(c));
    return d;
}
__device__ __forceinline__ float lo2(unsigned long long v) {
    return __uint_as_float((unsigned)(v & 0xffffffffu));
}
__device__ __forceinline__ float hi2(unsigned long long v) {
    return __uint_as_float((unsigned)(v >> 32));
}
#define ONE2 0x3f8000003f800000ull

// ---- 1. pack: A (float, 134 MB) -> bits (4 MB). Pure streaming. ----
// Word w (uint2) covers flat floats [64w, 64w+64): .x bit l = f[64w+2l], .y = odd.
__global__ void __launch_bounds__(256) pack_kernel(const float* __restrict__ A,
                                                   float* __restrict__ out) {
    int warp = threadIdx.x >> 5, lane = threadIdx.x & 31;
    size_t w0 = (size_t)blockIdx.x * 32 + warp * 4;          // 4 words per warp
    const float2* src = reinterpret_cast<const float2*>(A) + w0 * 32 + lane;

    float2 a0 = __ldcs(src);
    float2 a1 = __ldcs(src + 32);
    float2 a2 = __ldcs(src + 64);
    float2 a3 = __ldcs(src + 96);
    unsigned x0 = __ballot_sync(0xffffffffu, a0.x != 0.f);
    unsigned y0 = __ballot_sync(0xffffffffu, a0.y != 0.f);
    unsigned x1 = __ballot_sync(0xffffffffu, a1.x != 0.f);
    unsigned y1 = __ballot_sync(0xffffffffu, a1.y != 0.f);
    unsigned x2 = __ballot_sync(0xffffffffu, a2.x != 0.f);
    unsigned y2 = __ballot_sync(0xffffffffu, a2.y != 0.f);
    unsigned x3 = __ballot_sync(0xffffffffu, a3.x != 0.f);
    unsigned y3 = __ballot_sync(0xffffffffu, a3.y != 0.f);
    if (lane == 0) {
        uint4* dst = reinterpret_cast<uint4*>(g_Abits + w0);
        dst[0] = make_uint4(x0, y0, x1, y1);
        dst[1] = make_uint4(x2, y2, x3, y3);
    }

    if (blockIdx.x == 0) {       // zero out + bar
        if (threadIdx.x == 0) g_bar = 0u;
        for (int e = threadIdx.x; e < BB * (KK * DD + KK * KK); e += 256) out[e] = 0.f;
    }
}

// ---- 2/4. bit-fed A pass.
// MODE 0: V = pool(X) (computed in-block), epilogue writes P partials.
// MODE 1: V = L (g_s), epilogue contracts A_out partial -> atomicAdd(out).
template <int MODE>
__global__ void __launch_bounds__(128) bigpass6_kernel(const float* __restrict__ X,
                                                       float* __restrict__ out) {
    __shared__ float smem[8192];                 // 32 KB
    float* sV = smem;                            // [JCH*KK] = 8 KB
    uint2* sB = reinterpret_cast<uint2*>(smem + 2048);   // [4][JCH] = 4 KB
    int b = blockIdx.y, jc = blockIdx.z, tid = threadIdx.x;
    int warp = tid >> 5, lane = tid & 31;
    int j0 = jc * JCH;

    if (MODE == 0) {             // pool(X) chunk straight into SMEM
        const float4* xs = reinterpret_cast<const float4*>(X + ((size_t)b * NN + j0 + tid) * DD);
        float* dst = &sV[tid * KK];
#pragma unroll
        for (int p = 0; p < 16; p++) {
            float4 v = xs[p];
            dst[p] = (v.x + v.y + v.z + v.w) * 0.25f;
        }
    } else {
        const float4* src = reinterpret_cast<const float4*>(g_s + ((size_t)b * NN + j0) * KK);
        float4* dst = reinterpret_cast<float4*>(sV);
#pragma unroll
        for (int e = tid; e < JCH * KK / 4; e += 128) dst[e] = src[e];
    }
    {   // stage bits for this (i-block, j-chunk): 512 uint2
#pragma unroll
        for (int e = tid; e < 4 * JCH; e += 128) {
            int j = e >> 2, ws = e & 3;
            sB[ws * JCH + j] = g_Abits[((size_t)b * NN + j0 + j) * NW2 + blockIdx.x * 4 + ws];
        }
    }
    __syncthreads();

    unsigned lm = 1u << lane;
    unsigned long long acc[2][8];
#pragma unroll
    for (int ii = 0; ii < 2; ii++)
#pragma unroll
        for (int p = 0; p < 8; p++) acc[ii][p] = 0ull;

#pragma unroll 4
    for (int j = 0; j < JCH; j++) {
        uint2 w = sB[warp * JCH + j];
        unsigned long long aa0 = (w.x & lm) ? ONE2 : 0ull;
        unsigned long long aa1 = (w.y & lm) ? ONE2 : 0ull;
        const ulonglong2* vp = reinterpret_cast<const ulonglong2*>(sV + j * KK);
        ulonglong2 v0 = vp[0], v1 = vp[1], v2 = vp[2], v3 = vp[3];
        acc[0][0] = fma2(aa0, v0.x, acc[0][0]); acc[0][1] = fma2(aa0, v0.y, acc[0][1]);
        acc[0][2] = fma2(aa0, v1.x, acc[0][2]); acc[0][3] = fma2(aa0, v1.y, acc[0][3]);
        acc[0][4] = fma2(aa0, v2.x, acc[0][4]); acc[0][5] = fma2(aa0, v2.y, acc[0][5]);
        acc[0][6] = fma2(aa0, v3.x, acc[0][6]); acc[0][7] = fma2(aa0, v3.y, acc[0][7]);
        acc[1][0] = fma2(aa1, v0.x, acc[1][0]); acc[1][1] = fma2(aa1, v0.y, acc[1][1]);
        acc[1][2] = fma2(aa1, v1.x, acc[1][2]); acc[1][3] = fma2(aa1, v1.y, acc[1][3]);
        acc[1][4] = fma2(aa1, v2.x, acc[1][4]); acc[1][5] = fma2(aa1, v2.y, acc[1][5]);
        acc[1][6] = fma2(aa1, v3.x, acc[1][6]); acc[1][7] = fma2(aa1, v3.y, acc[1][7]);
    }

    // lane l of warp w owns output rows i = bx*256 + w*64 + 2l (+1)
    int i0 = blockIdx.x * IBLK + warp * 64 + lane * 2;

    if (MODE == 0) {
#pragma unroll
        for (int ii = 0; ii < 2; ii++) {
            float* P = g_P + (((size_t)b * NN + i0 + ii) * JC + jc) * KK;
            ulonglong2* Pv = reinterpret_cast<ulonglong2*>(P);
            Pv[0] = make_ulonglong2(acc[ii][0], acc[ii][1]);
            Pv[1] = make_ulonglong2(acc[ii][2], acc[ii][3]);
            Pv[2] = make_ulonglong2(acc[ii][4], acc[ii][5]);
            Pv[3] = make_ulonglong2(acc[ii][6], acc[ii][7]);
        }
    } else {
        float* sT = smem;            // [IBLK*KK] = 16 KB
        float* sL = smem + 4096;     // [IBLK*KK] = 16 KB
        __syncthreads();
#pragma unroll
        for (int ii = 0; ii < 2; ii++) {
            float* t = &sT[(i0 - blockIdx.x * IBLK + ii) * KK];
#pragma unroll
            for (int p = 0; p < 8; p++) { t[2*p] = lo2(acc[ii][p]); t[2*p+1] = hi2(acc[ii][p]); }
        }
        {
            const float4* Ls = reinterpret_cast<const float4*>(
                g_s + ((size_t)b * NN + blockIdx.x * IBLK) * KK);
            float4* dst = reinterpret_cast<float4*>(sL);
#pragma unroll
            for (int e = tid; e < IBLK * KK / 4; e += 128) dst[e] = Ls[e];
        }
        __syncthreads();
#pragma unroll
        for (int h = 0; h < 2; h++) {
            int pair = tid + h * 128;
            int k1 = pair >> 4, k2 = pair & 15;
            float s = 0.f;
#pragma unroll 8
            for (int i = 0; i < IBLK; i++)
                s += sL[i * KK + k1] * sT[i * KK + k2];
            atomicAdd(&out[(size_t)BB * KK * DD + b * KK * KK + pair], s);
        }
    }
}

// ---- helpers ----
__device__ __forceinline__ float4 quad_softmax(float q0, float q1, float q2, float q3) {
    float m = fmaxf(fmaxf(q0, q1), fmaxf(q2, q3));
    m = fmaxf(m, __shfl_xor_sync(0xffffffffu, m, 1));
    m = fmaxf(m, __shfl_xor_sync(0xffffffffu, m, 2));
    float e0 = expf(q0-m), e1 = expf(q1-m), e2 = expf(q2-m), e3 = expf(q3-m);
    float es = e0 + e1 + e2 + e3;
    es += __shfl_xor_sync(0xffffffffu, es, 1);
    es += __shfl_xor_sync(0xffffffffu, es, 2);
    float si = 1.0f / es;
    return make_float4(e0*si, e1*si, e2*si, e3*si);
}

__device__ __forceinline__ void grid_barrier(int tid, unsigned target) {
    __syncthreads();
    if (tid == 0) {
        __threadfence();
        atomicAdd(&g_bar, 1u);
        while (*(volatile unsigned*)&g_bar < target) { }
    }
    __syncthreads();
}

// ---- 3. mega: P-reduce -> U -> 5 iterations -> L; X_out via atomicAdd ----
__global__ void __launch_bounds__(512) mega_kernel(const float* __restrict__ X,
                                                   const float* __restrict__ wf,
                                                   const float* __restrict__ wc,
                                                   float* __restrict__ out) {
    __shared__ float sX[RPB * DD];
    __shared__ float ss[RPB * KK];
    __shared__ float sG[DD * KK];
    __shared__ float sM[KK * KK];
    __shared__ float cs[DD];
    int b = blockIdx.y, ch = blockIdx.x, tid = threadIdx.x;
    int lr = tid >> 2, q4 = tid & 3;
    size_t row = (size_t)b * NN + ch * RPB + lr;

    {
        const float4* src = reinterpret_cast<const float4*>(X + ((size_t)b * NN + ch * RPB) * DD);
        float4* dst = reinterpret_cast<float4*>(sX);
#pragma unroll
        for (int e = tid; e < RPB * DD / 4; e += 512) dst[e] = src[e];
    }
    if (tid < 256) {
        int k1 = tid >> 4, k2 = tid & 15;
        float mm = 0.f;
#pragma unroll
        for (int k = 0; k < KK; k++) mm += wf[k1*KK + k] * wc[k*KK + k2];
        sM[tid] = mm;
    }
    __syncthreads();

    float x[16];
#pragma unroll
    for (int p = 0; p < 4; p++) {
        float4 v = *reinterpret_cast<const float4*>(&sX[lr * DD + q4 * 16 + p * 4]);
        x[4*p] = v.x; x[4*p+1] = v.y; x[4*p+2] = v.z; x[4*p+3] = v.w;
    }
    float nsq = 0.f;
#pragma unroll
    for (int d = 0; d < 16; d++) nsq += x[d] * x[d];
    nsq += __shfl_xor_sync(0xffffffffu, nsq, 1);
    nsq += __shfl_xor_sync(0xffffffffu, nsq, 2);

    if (tid < 64) {
        float s = 0.f;
#pragma unroll 8
        for (int i = 0; i < RPB; i++) s += sX[i * DD + tid];
        g_cspart[(b * GCH + ch) * DD + tid] = s;
    }

    float4 u4 = make_float4(0.f, 0.f, 0.f, 0.f);
#pragma unroll
    for (int jc = 0; jc < JC; jc++) {
        float4 p = __ldcg(reinterpret_cast<const float4*>(g_P + (row * JC + jc) * KK + q4 * 4));
        u4.x += p.x; u4.y += p.y; u4.z += p.z; u4.w += p.w;
    }
    float lsum = u4.x + u4.y + u4.z + u4.w;
    lsum += __shfl_xor_sync(0xffffffffu, lsum, 1);
    lsum += __shfl_xor_sync(0xffffffffu, lsum, 2);
    float inv = 1.0f / lsum;
    float uq0 = tanhf(u4.x * inv), uq1 = tanhf(u4.y * inv);
    float uq2 = tanhf(u4.z * inv), uq3 = tanhf(u4.w * inv);
    {
        float4 sv = quad_softmax(uq0, uq1, uq2, uq3);
        *reinterpret_cast<float4*>(&ss[lr * KK + q4 * 4]) = sv;
    }
    __syncthreads();

    {
        int d = tid & 63, kb = (tid >> 6) * 2;
        float a0 = 0.f, a1 = 0.f;
#pragma unroll 4
        for (int i2 = 0; i2 < RPB; i2++) {
            float xx = sX[i2 * DD + d];
            a0 += xx * ss[i2 * KK + kb];
            a1 += xx * ss[i2 * KK + kb + 1];
        }
        float* gp = g_Gpart + (((size_t)b * GCH + ch) * DD + d) * KK + kb;
        gp[0] = a0; gp[1] = a1;
    }
    grid_barrier(tid, 1 * 128u);

    if (tid < 64) {
        float s = 0.f;
#pragma unroll
        for (int c = 0; c < GCH; c++) s += __ldcg(&g_cspart[(b * GCH + c) * DD + tid]);
        cs[tid] = s;
    }
    __syncthreads();
    float dot = 0.f;
#pragma unroll
    for (int d = 0; d < 16; d++) dot += x[d] * cs[q4 * 16 + d];
    dot += __shfl_xor_sync(0xffffffffu, dot, 1);
    dot += __shfl_xor_sync(0xffffffffu, dot, 2);
    float ninv = 1.0f / (dot - nsq);

    unsigned phase = 1;
#pragma unroll 1
    for (int it = 0; it < ITERS; it++) {
        bool last = (it == ITERS - 1);
        if (tid < 256) {
            float4 acc = make_float4(0.f, 0.f, 0.f, 0.f);
#pragma unroll
            for (int c2 = 0; c2 < GCH; c2++) {
                float4 p = __ldcg(reinterpret_cast<const float4*>(
                    g_Gpart + ((size_t)b * GCH + c2) * DD * KK + tid * 4));
                acc.x += p.x; acc.y += p.y; acc.z += p.z; acc.w += p.w;
            }
            *reinterpret_cast<float4*>(&sG[tid * 4]) = acc;
        }
        __syncthreads();

        float xg[KK];
#pragma unroll
        for (int k = 0; k < KK; k++) xg[k] = 0.f;
#pragma unroll
        for (int dd = 0; dd < 16; dd++) {
            float xd = x[dd];
            const float* g = &sG[(q4 * 16 + dd) * KK];
#pragma unroll
            for (int k = 0; k < KK; k++) xg[k] += xd * g[k];
        }
#pragma unroll
        for (int k = 0; k < KK; k++) {
            xg[k] += __shfl_xor_sync(0xffffffffu, xg[k], 1);
            xg[k] += __shfl_xor_sync(0xffffffffu, xg[k], 2);
        }

        float q0 = uq0, q1 = uq1, q2 = uq2, q3 = uq3;
#pragma unroll
        for (int k = 0; k < KK; k++) {
            float o = (xg[k] - nsq * ss[lr * KK + k]) * ninv;
            const float* Mr = &sM[k * KK + q4 * 4];
            q0 -= o * Mr[0]; q1 -= o * Mr[1]; q2 -= o * Mr[2]; q3 -= o * Mr[3];
        }
        float4 sv = quad_softmax(q0, q1, q2, q3);
        __syncthreads();
        *reinterpret_cast<float4*>(&ss[lr * KK + q4 * 4]) = sv;
        if (last) *reinterpret_cast<float4*>(g_s + row * KK + q4 * 4) = sv;
        __syncthreads();

        int d = tid & 63, kb = (tid >> 6) * 2;
        float a0 = 0.f, a1 = 0.f;
#pragma unroll 4
        for (int i2 = 0; i2 < RPB; i2++) {
            float xx = sX[i2 * DD + d];
            a0 += xx * ss[i2 * KK + kb];
            a1 += xx * ss[i2 * KK + kb + 1];
        }
        if (!last) {
            float* gp = g_Gpart + (((size_t)b * GCH + ch) * DD + d) * KK + kb;
            gp[0] = a0; gp[1] = a1;
            phase++;
            grid_barrier(tid, phase * 128u);
        } else {
            atomicAdd(&out[(size_t)b * KK * DD + (kb+0) * DD + d], a0);
            atomicAdd(&out[(size_t)b * KK * DD + (kb+1) * DD + d], a1);
        }
    }
}

extern "C" void kernel_launch(void* const* d_in, const int* in_sizes, int n_in,
                              void* d_out, int out_size) {
    const float* X  = (const float*)d_in[0];
    const float* A  = (const float*)d_in[1];
    const float* wf = (const float*)d_in[2];
    const float* wc = (const float*)d_in[3];
    float* out = (float*)d_out;

    pack_kernel<<<BB*NN*NW2/32, 256>>>(A, out);
    bigpass6_kernel<0><<<dim3(NN/IBLK, BB, JC), 128>>>(X, out);
    mega_kernel<<<dim3(GCH, BB), 512>>>(X, wf, wc, out);
    bigpass6_kernel<1><<<dim3(NN/IBLK, BB, JC), 128>>>(X, out);
}

// round 9
// speedup vs baseline: 1.1612x; 1.0067x over previous
#include <cuda_runtime.h>
#include <cstdint>
#include <math.h>

// StructPool: B=8, N=2048, D=64, K=16, 5 mean-field iterations.

#define BB 8
#define NN 2048
#define DD 64
#define KK 16
#define ITERS 5
#define GCH 16          // 128-row chunks (= mega blocks per batch)
#define JC 16           // j-chunks for the A passes
#define JCH 128
#define RPB 128
#define IBLK 512        // i-columns per bigpass block (128 thr x 4 cols)
#define NW4 (NN/128)    // uint4 words per j-row (16)

// ---- scratch ----
__device__ float g_cspart[BB*GCH*DD];
__device__ float g_s[BB*NN*KK];                 // L at the end
__device__ float g_P[(size_t)BB*NN*JC*KK];      // [row][jc][16], 16 MB
__device__ float g_Gpart[BB*GCH*DD*KK];
__device__ uint4 g_Abits[(size_t)BB*NN*NW4];    // bit-packed A, 4 MB
__device__ unsigned g_bar;

// ---- packed f32x2 ----
__device__ __forceinline__ unsigned long long pack2(float a) {
    unsigned long long r;
    asm("mov.b64 %0, {%1, %1};" : "=l"(r) : "f"(a));
    return r;
}
__device__ __forceinline__ unsigned long long fma2(unsigned long long a,
                                                   unsigned long long b,
                                                   unsigned long long c) {
    unsigned long long d;
    asm("fma.rn.f32x2 %0, %1, %2, %3;" : "=l"(d) : "l"(a), "l"(b), "l"(c));
    return d;
}
__device__ __forceinline__ float lo2(unsigned long long v) {
    return __uint_as_float((unsigned)(v & 0xffffffffu));
}
__device__ __forceinline__ float hi2(unsigned long long v) {
    return __uint_as_float((unsigned)(v >> 32));
}
#define ONE2 0x3f8000003f800000ull

// ---- 1. pack: A (float, 134 MB) -> uint4 bits (4 MB). Pure streaming. ----
// Word w covers 128 flat floats [128w, 128w+128): comp c bit l = f[128w + 4l + c].
__global__ void __launch_bounds__(256) pack_kernel(const float* __restrict__ A,
                                                   float* __restrict__ out) {
    int warp = threadIdx.x >> 5, lane = threadIdx.x & 31;
    size_t w0 = (size_t)blockIdx.x * 32 + warp * 4;          // 4 words per warp
    const float4* src = reinterpret_cast<const float4*>(A) + w0 * 32 + lane;

    uint4 r[4];
#pragma unroll
    for (int p = 0; p < 4; p++) {
        float4 a = __ldcs(src + p * 32);
        r[p].x = __ballot_sync(0xffffffffu, a.x != 0.f);
        r[p].y = __ballot_sync(0xffffffffu, a.y != 0.f);
        r[p].z = __ballot_sync(0xffffffffu, a.z != 0.f);
        r[p].w = __ballot_sync(0xffffffffu, a.w != 0.f);
    }
    if (lane < 4) g_Abits[w0 + lane] = r[0];   // lane-indexed scatter of the 4 words
    // NOTE: ballots computed by all lanes; r[p] identical across warp. Store 4 words:
    if (lane == 0) {
        g_Abits[w0 + 0] = r[0]; g_Abits[w0 + 1] = r[1];
        g_Abits[w0 + 2] = r[2]; g_Abits[w0 + 3] = r[3];
    }

    if (blockIdx.x == 0) {       // zero out + bar
        if (threadIdx.x == 0) g_bar = 0u;
        for (int e = threadIdx.x; e < BB * (KK * DD + KK * KK); e += 256) out[e] = 0.f;
    }
}

// ---- 2/4. bit-fed A pass, 4 cols/thread.
// MODE 0: V = pool(X) (computed in-block), epilogue writes P partials.
// MODE 1: V = L (g_s), epilogue contracts A_out partial -> atomicAdd(out).
template <int MODE>
__global__ void __launch_bounds__(128) bigpass7_kernel(const float* __restrict__ X,
                                                       float* __restrict__ out) {
    __shared__ float smem[8192];                 // 32 KB
    float* sV = smem;                            // [JCH*KK] = 8 KB
    uint4* sB = reinterpret_cast<uint4*>(smem + 2048);   // [4][JCH] = 8 KB
    int b = blockIdx.y, jc = blockIdx.z, tid = threadIdx.x;
    int warp = tid >> 5, lane = tid & 31;
    int j0 = jc * JCH;

    if (MODE == 0) {             // pool(X) chunk straight into SMEM
        const float4* xs = reinterpret_cast<const float4*>(X + ((size_t)b * NN + j0 + tid) * DD);
        float* dst = &sV[tid * KK];
#pragma unroll
        for (int p = 0; p < 16; p++) {
            float4 v = xs[p];
            dst[p] = (v.x + v.y + v.z + v.w) * 0.25f;
        }
    } else {
        const float4* src = reinterpret_cast<const float4*>(g_s + ((size_t)b * NN + j0) * KK);
        float4* dst = reinterpret_cast<float4*>(sV);
#pragma unroll
        for (int e = tid; e < JCH * KK / 4; e += 128) dst[e] = src[e];
    }
    {   // stage bits: word (bx*4 + w) of each j row, for warp w
#pragma unroll
        for (int e = tid; e < 4 * JCH; e += 128) {
            int j = e >> 2, ws = e & 3;
            sB[ws * JCH + j] = g_Abits[((size_t)b * NN + j0 + j) * NW4 + blockIdx.x * 4 + ws];
        }
    }
    __syncthreads();

    unsigned lm = 1u << lane;
    unsigned long long acc[4][8];
#pragma unroll
    for (int c = 0; c < 4; c++)
#pragma unroll
        for (int p = 0; p < 8; p++) acc[c][p] = 0ull;

#pragma unroll 2
    for (int j = 0; j < JCH; j++) {
        uint4 w = sB[warp * JCH + j];
        unsigned long long aa0 = (w.x & lm) ? ONE2 : 0ull;
        unsigned long long aa1 = (w.y & lm) ? ONE2 : 0ull;
        unsigned long long aa2 = (w.z & lm) ? ONE2 : 0ull;
        unsigned long long aa3 = (w.w & lm) ? ONE2 : 0ull;
        const ulonglong2* vp = reinterpret_cast<const ulonglong2*>(sV + j * KK);
        ulonglong2 v0 = vp[0], v1 = vp[1], v2 = vp[2], v3 = vp[3];
        acc[0][0] = fma2(aa0, v0.x, acc[0][0]); acc[0][1] = fma2(aa0, v0.y, acc[0][1]);
        acc[0][2] = fma2(aa0, v1.x, acc[0][2]); acc[0][3] = fma2(aa0, v1.y, acc[0][3]);
        acc[0][4] = fma2(aa0, v2.x, acc[0][4]); acc[0][5] = fma2(aa0, v2.y, acc[0][5]);
        acc[0][6] = fma2(aa0, v3.x, acc[0][6]); acc[0][7] = fma2(aa0, v3.y, acc[0][7]);
        acc[1][0] = fma2(aa1, v0.x, acc[1][0]); acc[1][1] = fma2(aa1, v0.y, acc[1][1]);
        acc[1][2] = fma2(aa1, v1.x, acc[1][2]); acc[1][3] = fma2(aa1, v1.y, acc[1][3]);
        acc[1][4] = fma2(aa1, v2.x, acc[1][4]); acc[1][5] = fma2(aa1, v2.y, acc[1][5]);
        acc[1][6] = fma2(aa1, v3.x, acc[1][6]); acc[1][7] = fma2(aa1, v3.y, acc[1][7]);
        acc[2][0] = fma2(aa2, v0.x, acc[2][0]); acc[2][1] = fma2(aa2, v0.y, acc[2][1]);
        acc[2][2] = fma2(aa2, v1.x, acc[2][2]); acc[2][3] = fma2(aa2, v1.y, acc[2][3]);
        acc[2][4] = fma2(aa2, v2.x, acc[2][4]); acc[2][5] = fma2(aa2, v2.y, acc[2][5]);
        acc[2][6] = fma2(aa2, v3.x, acc[2][6]); acc[2][7] = fma2(aa2, v3.y, acc[2][7]);
        acc[3][0] = fma2(aa3, v0.x, acc[3][0]); acc[3][1] = fma2(aa3, v0.y, acc[3][1]);
        acc[3][2] = fma2(aa3, v1.x, acc[3][2]); acc[3][3] = fma2(aa3, v1.y, acc[3][3]);
        acc[3][4] = fma2(aa3, v2.x, acc[3][4]); acc[3][5] = fma2(aa3, v2.y, acc[3][5]);
        acc[3][6] = fma2(aa3, v3.x, acc[3][6]); acc[3][7] = fma2(aa3, v3.y, acc[3][7]);
    }

    // thread's 4 output cols: i = bx*512 + warp*128 + 4*lane + c  (consecutive in c)
    int iloc = warp * 128 + lane * 4;

    if (MODE == 0) {
        int i0 = blockIdx.x * IBLK + iloc;
#pragma unroll
        for (int c = 0; c < 4; c++) {
            float* P = g_P + (((size_t)b * NN + i0 + c) * JC + jc) * KK;
            ulonglong2* Pv = reinterpret_cast<ulonglong2*>(P);
            Pv[0] = make_ulonglong2(acc[c][0], acc[c][1]);
            Pv[1] = make_ulonglong2(acc[c][2], acc[c][3]);
            Pv[2] = make_ulonglong2(acc[c][4], acc[c][5]);
            Pv[3] = make_ulonglong2(acc[c][6], acc[c][7]);
        }
    } else {
        // A_out partial in two 256-row halves (SMEM reuse: sT 16KB + sL 16KB)
        float* sT = smem;
        float* sL = smem + 4096;
        float r0 = 0.f, r1 = 0.f;
        int k1a = tid >> 4, k2a = tid & 15;            // pair tid
        int k1b = (tid + 128) >> 4, k2b = tid & 15;    // pair tid+128
#pragma unroll
        for (int h = 0; h < 2; h++) {
            __syncthreads();
            if ((warp >> 1) == h) {
                int lc = (warp & 1) * 128 + lane * 4;
#pragma unroll
                for (int c = 0; c < 4; c++) {
                    float* t = &sT[(lc + c) * KK];
#pragma unroll
                    for (int p = 0; p < 8; p++) {
                        t[2*p] = lo2(acc[c][p]); t[2*p+1] = hi2(acc[c][p]);
                    }
                }
            }
            {
                const float4* Ls = reinterpret_cast<const float4*>(
                    g_s + ((size_t)b * NN + blockIdx.x * IBLK + h * 256) * KK);
                float4* dst = reinterpret_cast<float4*>(sL);
#pragma unroll
                for (int e = tid; e < 256 * KK / 4; e += 128) dst[e] = Ls[e];
            }
            __syncthreads();
#pragma unroll 8
            for (int i = 0; i < 256; i++) {
                float t2a = sT[i * KK + k2a];
                r0 += sL[i * KK + k1a] * t2a;
                r1 += sL[i * KK + k1b] * t2a;   // k2b == k2a
            }
        }
        float* ao = &out[(size_t)BB * KK * DD + b * KK * KK];
        atomicAdd(&ao[k1a * KK + k2a], r0);
        atomicAdd(&ao[k1b * KK + k2b], r1);
    }
}

// ---- helpers ----
__device__ __forceinline__ float4 quad_softmax(float q0, float q1, float q2, float q3) {
    float m = fmaxf(fmaxf(q0, q1), fmaxf(q2, q3));
    m = fmaxf(m, __shfl_xor_sync(0xffffffffu, m, 1));
    m = fmaxf(m, __shfl_xor_sync(0xffffffffu, m, 2));
    float e0 = expf(q0-m), e1 = expf(q1-m), e2 = expf(q2-m), e3 = expf(q3-m);
    float es = e0 + e1 + e2 + e3;
    es += __shfl_xor_sync(0xffffffffu, es, 1);
    es += __shfl_xor_sync(0xffffffffu, es, 2);
    float si = 1.0f / es;
    return make_float4(e0*si, e1*si, e2*si, e3*si);
}

__device__ __forceinline__ void grid_barrier(int tid, unsigned target) {
    __syncthreads();
    if (tid == 0) {
        __threadfence();
        atomicAdd(&g_bar, 1u);
        while (*(volatile unsigned*)&g_bar < target) { }
    }
    __syncthreads();
}

// ---- 3. mega: P-reduce -> U -> 5 iterations -> L; X_out via atomicAdd ----
__global__ void __launch_bounds__(512) mega_kernel(const float* __restrict__ X,
                                                   const float* __restrict__ wf,
                                                   const float* __restrict__ wc,
                                                   float* __restrict__ out) {
    __shared__ float sX[RPB * DD];
    __shared__ float ss[RPB * KK];
    __shared__ float sG[DD * KK];
    __shared__ float sM[KK * KK];
    __shared__ float cs[DD];
    int b = blockIdx.y, ch = blockIdx.x, tid = threadIdx.x;
    int lr = tid >> 2, q4 = tid & 3;
    size_t row = (size_t)b * NN + ch * RPB + lr;

    {
        const float4* src = reinterpret_cast<const float4*>(X + ((size_t)b * NN + ch * RPB) * DD);
        float4* dst = reinterpret_cast<float4*>(sX);
#pragma unroll
        for (int e = tid; e < RPB * DD / 4; e += 512) dst[e] = src[e];
    }
    if (tid < 256) {
        int k1 = tid >> 4, k2 = tid & 15;
        float mm = 0.f;
#pragma unroll
        for (int k = 0; k < KK; k++) mm += wf[k1*KK + k] * wc[k*KK + k2];
        sM[tid] = mm;
    }
    __syncthreads();

    float x[16];
#pragma unroll
    for (int p = 0; p < 4; p++) {
        float4 v = *reinterpret_cast<const float4*>(&sX[lr * DD + q4 * 16 + p * 4]);
        x[4*p] = v.x; x[4*p+1] = v.y; x[4*p+2] = v.z; x[4*p+3] = v.w;
    }
    float nsq = 0.f;
#pragma unroll
    for (int d = 0; d < 16; d++) nsq += x[d] * x[d];
    nsq += __shfl_xor_sync(0xffffffffu, nsq, 1);
    nsq += __shfl_xor_sync(0xffffffffu, nsq, 2);

    if (tid < 64) {
        float s = 0.f;
#pragma unroll 8
        for (int i = 0; i < RPB; i++) s += sX[i * DD + tid];
        g_cspart[(b * GCH + ch) * DD + tid] = s;
    }

    float4 u4 = make_float4(0.f, 0.f, 0.f, 0.f);
#pragma unroll
    for (int jc = 0; jc < JC; jc++) {
        float4 p = __ldcg(reinterpret_cast<const float4*>(g_P + (row * JC + jc) * KK + q4 * 4));
        u4.x += p.x; u4.y += p.y; u4.z += p.z; u4.w += p.w;
    }
    float lsum = u4.x + u4.y + u4.z + u4.w;
    lsum += __shfl_xor_sync(0xffffffffu, lsum, 1);
    lsum += __shfl_xor_sync(0xffffffffu, lsum, 2);
    float inv = 1.0f / lsum;
    float uq0 = tanhf(u4.x * inv), uq1 = tanhf(u4.y * inv);
    float uq2 = tanhf(u4.z * inv), uq3 = tanhf(u4.w * inv);
    {
        float4 sv = quad_softmax(uq0, uq1, uq2, uq3);
        *reinterpret_cast<float4*>(&ss[lr * KK + q4 * 4]) = sv;
    }
    __syncthreads();

    {
        int d = tid & 63, kb = (tid >> 6) * 2;
        float a0 = 0.f, a1 = 0.f;
#pragma unroll 4
        for (int i2 = 0; i2 < RPB; i2++) {
            float xx = sX[i2 * DD + d];
            a0 += xx * ss[i2 * KK + kb];
            a1 += xx * ss[i2 * KK + kb + 1];
        }
        float* gp = g_Gpart + (((size_t)b * GCH + ch) * DD + d) * KK + kb;
        gp[0] = a0; gp[1] = a1;
    }
    grid_barrier(tid, 1 * 128u);

    if (tid < 64) {
        float s = 0.f;
#pragma unroll
        for (int c = 0; c < GCH; c++) s += __ldcg(&g_cspart[(b * GCH + c) * DD + tid]);
        cs[tid] = s;
    }
    __syncthreads();
    float dot = 0.f;
#pragma unroll
    for (int d = 0; d < 16; d++) dot += x[d] * cs[q4 * 16 + d];
    dot += __shfl_xor_sync(0xffffffffu, dot, 1);
    dot += __shfl_xor_sync(0xffffffffu, dot, 2);
    float ninv = 1.0f / (dot - nsq);

    unsigned phase = 1;
#pragma unroll 1
    for (int it = 0; it < ITERS; it++) {
        bool last = (it == ITERS - 1);
        if (tid < 256) {
            float4 acc = make_float4(0.f, 0.f, 0.f, 0.f);
#pragma unroll
            for (int c2 = 0; c2 < GCH; c2++) {
                float4 p = __ldcg(reinterpret_cast<const float4*>(
                    g_Gpart + ((size_t)b * GCH + c2) * DD * KK + tid * 4));
                acc.x += p.x; acc.y += p.y; acc.z += p.z; acc.w += p.w;
            }
            *reinterpret_cast<float4*>(&sG[tid * 4]) = acc;
        }
        __syncthreads();

        float xg[KK];
#pragma unroll
        for (int k = 0; k < KK; k++) xg[k] = 0.f;
#pragma unroll
        for (int dd = 0; dd < 16; dd++) {
            float xd = x[dd];
            const float* g = &sG[(q4 * 16 + dd) * KK];
#pragma unroll
            for (int k = 0; k < KK; k++) xg[k] += xd * g[k];
        }
#pragma unroll
        for (int k = 0; k < KK; k++) {
            xg[k] += __shfl_xor_sync(0xffffffffu, xg[k], 1);
            xg[k] += __shfl_xor_sync(0xffffffffu, xg[k], 2);
        }

        float q0 = uq0, q1 = uq1, q2 = uq2, q3 = uq3;
#pragma unroll
        for (int k = 0; k < KK; k++) {
            float o = (xg[k] - nsq * ss[lr * KK + k]) * ninv;
            const float* Mr = &sM[k * KK + q4 * 4];
            q0 -= o * Mr[0]; q1 -= o * Mr[1]; q2 -= o * Mr[2]; q3 -= o * Mr[3];
        }
        float4 sv = quad_softmax(q0, q1, q2, q3);
        __syncthreads();
        *reinterpret_cast<float4*>(&ss[lr * KK + q4 * 4]) = sv;
        if (last) *reinterpret_cast<float4*>(g_s + row * KK + q4 * 4) = sv;
        __syncthreads();

        int d = tid & 63, kb = (tid >> 6) * 2;
        float a0 = 0.f, a1 = 0.f;
#pragma unroll 4
        for (int i2 = 0; i2 < RPB; i2++) {
            float xx = sX[i2 * DD + d];
            a0 += xx * ss[i2 * KK + kb];
            a1 += xx * ss[i2 * KK + kb + 1];
        }
        if (!last) {
            float* gp = g_Gpart + (((size_t)b * GCH + ch) * DD + d) * KK + kb;
            gp[0] = a0; gp[1] = a1;
            phase++;
            grid_barrier(tid, phase * 128u);
        } else {
            atomicAdd(&out[(size_t)b * KK * DD + (kb+0) * DD + d], a0);
            atomicAdd(&out[(size_t)b * KK * DD + (kb+1) * DD + d], a1);
        }
    }
}

extern "C" void kernel_launch(void* const* d_in, const int* in_sizes, int n_in,
                              void* d_out, int out_size) {
    const float* X  = (const float*)d_in[0];
    const float* A  = (const float*)d_in[1];
    const float* wf = (const float*)d_in[2];
    const float* wc = (const float*)d_in[3];
    float* out = (float*)d_out;

    pack_kernel<<<BB*NN*NW4/32, 256>>>(A, out);
    bigpass7_kernel<0><<<dim3(NN/IBLK, BB, JC), 128>>>(X, out);
    mega_kernel<<<dim3(GCH, BB), 512>>>(X, wf, wc, out);
    bigpass7_kernel<1><<<dim3(NN/IBLK, BB, JC), 128>>>(X, out);
}